// round 2
// baseline (speedup 1.0000x reference)
#include <cuda_runtime.h>

#define T_STEPS 512
#define BATCH   4096
#define HID     16

// Scratch for h2[t] (layer-2 LSTM outputs for batch 4095). __device__ global:
// no allocation in kernel_launch.
__device__ float g_h2[T_STEPS * HID];

__device__ __forceinline__ float sigf(float x) {
    // 1 / (1 + exp(-x)), fast paths (MUFU.EX2 + MUFU.RCP)
    return __fdividef(1.0f, 1.0f + __expf(-x));
}
__device__ __forceinline__ float tanh_fast(float x) {
    // tanh(x) = 2*sigmoid(2x) - 1
    return __fdividef(2.0f, 1.0f + __expf(-2.0f * x)) - 1.0f;
}

// One warp runs BOTH LSTM layers, software-pipelined:
//   lanes 0..15  : layer-0 hidden unit u = lane      (state h0, c0)
//   lanes 16..31 : layer-1 hidden unit u = lane - 16 (state h1, c1), one step behind
// Iteration i computes layer-0 step i and layer-1 step i-1.
__global__ void __launch_bounds__(32, 1) lstm_recur_kernel(
    const float* __restrict__ x,
    const float* __restrict__ Wih0, const float* __restrict__ Whh0,
    const float* __restrict__ bih0, const float* __restrict__ bhh0,
    const float* __restrict__ Wih1, const float* __restrict__ Whh1,
    const float* __restrict__ bih1, const float* __restrict__ bhh1)
{
    __shared__ float x_sh[T_STEPS];
    const int lane = threadIdx.x;

    // ---- gather x[:, BATCH-1, 0] (stride-BATCH floats) into shared ----
    float xg[16];
#pragma unroll
    for (int r = 0; r < 16; r++)
        xg[r] = x[(lane + 32 * r) * BATCH + (BATCH - 1)];
#pragma unroll
    for (int r = 0; r < 16; r++)
        x_sh[lane + 32 * r] = xg[r];
    __syncwarp();

    const bool is0 = (lane < 16);
    const int  u   = is0 ? lane : lane - 16;

    // Per-lane weights, fully register-resident.
    // gate g in {0:i, 1:f, 2:g, 3:o}; gate row index gi = g*16 + u
    float Wr[4][16];   // recurrent weights (Whh0 rows for layer0 lanes, Whh1 for layer1)
    float Wi[4][16];   // input-dot weights (zeros for layer0 lanes, Wih1 rows for layer1)
    float bias[4];     // bih + bhh
    float wx[4];       // layer0: Wih0[gi] (input dim = 1); layer1: 0

#pragma unroll
    for (int g = 0; g < 4; g++) {
        const int gi = g * 16 + u;
        if (is0) {
#pragma unroll
            for (int k = 0; k < 16; k++) {
                Wr[g][k] = Whh0[gi * 16 + k];
                Wi[g][k] = 0.0f;
            }
            bias[g] = bih0[gi] + bhh0[gi];
            wx[g]   = Wih0[gi];
        } else {
#pragma unroll
            for (int k = 0; k < 16; k++) {
                Wr[g][k] = Whh1[gi * 16 + k];
                Wi[g][k] = Wih1[gi * 16 + k];
            }
            bias[g] = bih1[gi] + bhh1[gi];
            wx[g]   = 0.0f;
        }
    }

    float h = 0.0f, c = 0.0f;

    // i = 0..T_STEPS: layer0 active for i < T, layer1 active (computing step i-1) for i >= 1
    for (int i = 0; i <= T_STEPS; i++) {
        const float xval = x_sh[i < T_STEPS ? i : T_STEPS - 1];

        float a0 = fmaf(wx[0], xval, bias[0]);
        float a1 = fmaf(wx[1], xval, bias[1]);
        float a2 = fmaf(wx[2], xval, bias[2]);
        float a3 = fmaf(wx[3], xval, bias[3]);

#pragma unroll
        for (int k = 0; k < 16; k++) {
            // h0[i-1]_k lives on lane k; h1[i-2]_k lives on lane 16+k
            const float va = __shfl_sync(0xffffffffu, h, k);        // h0_k
            const float vb = __shfl_sync(0xffffffffu, h, 16 + k);   // h1_k
            const float sel = is0 ? va : vb;                        // recurrent operand
            a0 = fmaf(Wr[0][k], sel, a0);  a0 = fmaf(Wi[0][k], va, a0);
            a1 = fmaf(Wr[1][k], sel, a1);  a1 = fmaf(Wi[1][k], va, a1);
            a2 = fmaf(Wr[2][k], sel, a2);  a2 = fmaf(Wi[2][k], va, a2);
            a3 = fmaf(Wr[3][k], sel, a3);  a3 = fmaf(Wi[3][k], va, a3);
        }

        const float ig = sigf(a0);
        const float fg = sigf(a1);
        const float gg = tanh_fast(a2);
        const float og = sigf(a3);

        const bool upd = is0 ? (i < T_STEPS) : (i > 0);
        if (upd) {
            c = fmaf(fg, c, ig * gg);
            h = og * tanh_fast(c);
        }
        // lanes >= 16 just produced h2[i-1]
        if (!is0 && i > 0)
            g_h2[(i - 1) * HID + u] = h;
    }
}

// Per-timestep MLP: 16 -> 64 (relu) -> 32 (relu) -> 1. One block per timestep.
__global__ void __launch_bounds__(64) mlp_kernel(
    const float* __restrict__ W1, const float* __restrict__ b1,
    const float* __restrict__ W2, const float* __restrict__ b2,
    const float* __restrict__ W3, const float* __restrict__ b3,
    float* __restrict__ out)
{
    __shared__ float hsh[HID];
    __shared__ float z1[64];
    const int t   = blockIdx.x;
    const int tid = threadIdx.x;

    if (tid < HID) hsh[tid] = g_h2[t * HID + tid];
    __syncthreads();

    // layer: 16 -> 64, relu
    float a = b1[tid];
#pragma unroll
    for (int k = 0; k < HID; k++)
        a = fmaf(W1[tid * HID + k], hsh[k], a);
    z1[tid] = fmaxf(a, 0.0f);
    __syncthreads();

    // layer: 64 -> 32, relu, then dot with W3 (1x32) + b3
    if (tid < 32) {
        float a2 = b2[tid];
#pragma unroll
        for (int k = 0; k < 64; k++)
            a2 = fmaf(W2[tid * 64 + k], z1[k], a2);
        float v = fmaxf(a2, 0.0f) * W3[tid];
#pragma unroll
        for (int off = 16; off; off >>= 1)
            v += __shfl_xor_sync(0xffffffffu, v, off);
        if (tid == 0) out[t] = v + b3[0];
    }
}

extern "C" void kernel_launch(void* const* d_in, const int* in_sizes, int n_in,
                              void* d_out, int out_size)
{
    const float* x    = (const float*)d_in[0];
    const float* Wih0 = (const float*)d_in[1];
    const float* Whh0 = (const float*)d_in[2];
    const float* bih0 = (const float*)d_in[3];
    const float* bhh0 = (const float*)d_in[4];
    const float* Wih1 = (const float*)d_in[5];
    const float* Whh1 = (const float*)d_in[6];
    const float* bih1 = (const float*)d_in[7];
    const float* bhh1 = (const float*)d_in[8];
    const float* W1   = (const float*)d_in[9];
    const float* b1   = (const float*)d_in[10];
    const float* W2   = (const float*)d_in[11];
    const float* b2   = (const float*)d_in[12];
    const float* W3   = (const float*)d_in[13];
    const float* b3   = (const float*)d_in[14];
    float* out = (float*)d_out;

    lstm_recur_kernel<<<1, 32>>>(x, Wih0, Whh0, bih0, bhh0,
                                 Wih1, Whh1, bih1, bhh1);
    mlp_kernel<<<T_STEPS, 64>>>(W1, b1, W2, b2, W3, b3, out);
}

// round 3
// speedup vs baseline: 1.1153x; 1.1153x over previous
#include <cuda_runtime.h>

#define T_STEPS 512
#define BATCH   4096
#define HID     16

// h2[t] for batch element BATCH-1 (the only one the output depends on).
__device__ float g_h2[T_STEPS * HID];

typedef unsigned long long ull;

__device__ __forceinline__ ull ffma2(ull a, ull b, ull c) {
    ull d;
    asm("fma.rn.f32x2 %0, %1, %2, %3;" : "=l"(d) : "l"(a), "l"(b), "l"(c));
    return d;
}
__device__ __forceinline__ ull fadd2(ull a, ull b) {
    ull d;
    asm("add.rn.f32x2 %0, %1, %2;" : "=l"(d) : "l"(a), "l"(b));
    return d;
}
__device__ __forceinline__ float hsum2(ull a) {
    float lo, hi;
    asm("mov.b64 {%0, %1}, %2;" : "=f"(lo), "=f"(hi) : "l"(a));
    return lo + hi;
}

__device__ __forceinline__ float sigf(float x) {
    return __fdividef(1.0f, 1.0f + __expf(-x));
}
__device__ __forceinline__ float tanh_fast(float x) {
    return __fdividef(2.0f, 1.0f + __expf(-2.0f * x)) - 1.0f;
}

// One warp, both LSTM layers software-pipelined:
//   lanes 0..15  : layer-0 unit u = lane
//   lanes 16..31 : layer-1 unit u = lane-16, one step behind.
// Dot products computed with packed fma.rn.f32x2; h exchanged via
// double-buffered shared memory (1 STS + syncwarp + 8 LDS.128 per iter).
__global__ void __launch_bounds__(32, 1) lstm_recur_kernel(
    const float* __restrict__ x,
    const float* __restrict__ Wih0, const float* __restrict__ Whh0,
    const float* __restrict__ bih0, const float* __restrict__ bhh0,
    const float* __restrict__ Wih1, const float* __restrict__ Whh1,
    const float* __restrict__ bih1, const float* __restrict__ bhh1)
{
    __shared__ float x_sh[T_STEPS];
    __shared__ __align__(16) float hbuf[2][32];
    const int lane = threadIdx.x;

    // gather x[:, BATCH-1, 0] into shared
    float xg[16];
#pragma unroll
    for (int r = 0; r < 16; r++)
        xg[r] = x[(lane + 32 * r) * BATCH + (BATCH - 1)];
#pragma unroll
    for (int r = 0; r < 16; r++)
        x_sh[lane + 32 * r] = xg[r];

    const bool is0 = (lane < 16);
    const int  u   = is0 ? lane : lane - 16;

    // Register-resident packed weights.
    // accR path: recurrent weights (Whh0 for layer0 lanes, Whh1 for layer1),
    //            operand = hbuf[rbase .. rbase+15]
    // accB path: layer1 input weights Wih1 (zeros on layer0 lanes),
    //            operand = hbuf[0..15] (h0)
    ull Wr2[4][8], Wb2[4][8];
    float bias[4], wx[4];
    const ull* WhhP = (const ull*)(is0 ? Whh0 : Whh1);
    const ull* WihP = (const ull*)Wih1;
#pragma unroll
    for (int g = 0; g < 4; g++) {
        const int gi = g * 16 + u;
#pragma unroll
        for (int kp = 0; kp < 8; kp++) {
            Wr2[g][kp] = WhhP[gi * 8 + kp];
            Wb2[g][kp] = is0 ? 0ull : WihP[gi * 8 + kp];
        }
        bias[g] = is0 ? (bih0[gi] + bhh0[gi]) : (bih1[gi] + bhh1[gi]);
        wx[g]   = is0 ? Wih0[gi] : 0.0f;
    }

    const int rbase = is0 ? 0 : 16;
    float h = 0.0f, c = 0.0f;

#pragma unroll 2
    for (int i = 0; i <= T_STEPS; i++) {
        const float xval = x_sh[i < T_STEPS ? i : T_STEPS - 1];
        float* buf = hbuf[i & 1];
        buf[lane] = h;
        __syncwarp();

        const ulonglong2* pr = (const ulonglong2*)(buf + rbase);
        const ulonglong2* pa = (const ulonglong2*)buf;

        ull accR[4] = {0ull, 0ull, 0ull, 0ull};
        ull accB[4] = {0ull, 0ull, 0ull, 0ull};
#pragma unroll
        for (int j = 0; j < 4; j++) {
            const ulonglong2 rv = pr[j];   // h-pairs (2k, 2k+1), recurrent operand
            const ulonglong2 av = pa[j];   // h0-pairs, layer-1 input operand
#pragma unroll
            for (int g = 0; g < 4; g++) {
                accR[g] = ffma2(Wr2[g][2 * j    ], rv.x, accR[g]);
                accR[g] = ffma2(Wr2[g][2 * j + 1], rv.y, accR[g]);
                accB[g] = ffma2(Wb2[g][2 * j    ], av.x, accB[g]);
                accB[g] = ffma2(Wb2[g][2 * j + 1], av.y, accB[g]);
            }
        }

        float a[4];
#pragma unroll
        for (int g = 0; g < 4; g++)
            a[g] = hsum2(fadd2(accR[g], accB[g])) + fmaf(wx[g], xval, bias[g]);

        const float ig = sigf(a[0]);
        const float fg = sigf(a[1]);
        const float gg = tanh_fast(a[2]);
        const float og = sigf(a[3]);

        const bool upd = is0 ? (i < T_STEPS) : (i > 0);
        if (upd) {
            c = fmaf(fg, c, ig * gg);
            h = og * tanh_fast(c);
        }
        if (!is0 && i > 0)
            g_h2[(i - 1) * HID + u] = h;
    }
}

// MLP 16 -> 64 (relu) -> 32 (relu) -> 1, 8 timesteps per block so the
// weight loads amortize. W2 staged in shared with stride-65 padding
// (stride 64 would be a 32-way bank conflict).
#define MLP_TPB   64
#define MLP_TSPB  8
__global__ void __launch_bounds__(MLP_TPB) mlp_kernel(
    const float* __restrict__ W1, const float* __restrict__ b1,
    const float* __restrict__ W2, const float* __restrict__ b2,
    const float* __restrict__ W3, const float* __restrict__ b3,
    float* __restrict__ out)
{
    __shared__ float w2sh[32 * 65];
    __shared__ float hsh[HID];
    __shared__ float z1[64];
    const int tid = threadIdx.x;

    for (int idx = tid; idx < 32 * 64; idx += MLP_TPB)
        w2sh[(idx >> 6) * 65 + (idx & 63)] = W2[idx];

    float w1r[HID];
#pragma unroll
    for (int k = 0; k < HID; k++) w1r[k] = W1[tid * HID + k];
    const float b1r = b1[tid];
    const float b2r = (tid < 32) ? b2[tid] : 0.0f;
    const float w3r = (tid < 32) ? W3[tid] : 0.0f;
    const float b3r = b3[0];
    __syncthreads();

    for (int j = 0; j < MLP_TSPB; j++) {
        const int t = blockIdx.x * MLP_TSPB + j;
        if (tid < HID) hsh[tid] = g_h2[t * HID + tid];
        __syncthreads();

        float acc = b1r;
#pragma unroll
        for (int k = 0; k < HID; k++)
            acc = fmaf(w1r[k], hsh[k], acc);
        z1[tid] = fmaxf(acc, 0.0f);
        __syncthreads();

        if (tid < 32) {
            float a2 = b2r;
#pragma unroll
            for (int k = 0; k < 64; k++)
                a2 = fmaf(w2sh[tid * 65 + k], z1[k], a2);
            float v = fmaxf(a2, 0.0f) * w3r;
#pragma unroll
            for (int off = 16; off; off >>= 1)
                v += __shfl_xor_sync(0xffffffffu, v, off);
            if (tid == 0) out[t] = v + b3r;
        }
        __syncthreads();
    }
}

extern "C" void kernel_launch(void* const* d_in, const int* in_sizes, int n_in,
                              void* d_out, int out_size)
{
    const float* x    = (const float*)d_in[0];
    const float* Wih0 = (const float*)d_in[1];
    const float* Whh0 = (const float*)d_in[2];
    const float* bih0 = (const float*)d_in[3];
    const float* bhh0 = (const float*)d_in[4];
    const float* Wih1 = (const float*)d_in[5];
    const float* Whh1 = (const float*)d_in[6];
    const float* bih1 = (const float*)d_in[7];
    const float* bhh1 = (const float*)d_in[8];
    const float* W1   = (const float*)d_in[9];
    const float* b1   = (const float*)d_in[10];
    const float* W2   = (const float*)d_in[11];
    const float* b2   = (const float*)d_in[12];
    const float* W3   = (const float*)d_in[13];
    const float* b3   = (const float*)d_in[14];
    float* out = (float*)d_out;

    lstm_recur_kernel<<<1, 32>>>(x, Wih0, Whh0, bih0, bhh0,
                                 Wih1, Whh1, bih1, bhh1);
    mlp_kernel<<<T_STEPS / MLP_TSPB, MLP_TPB>>>(W1, b1, W2, b2, W3, b3, out);
}

// round 4
// speedup vs baseline: 1.2219x; 1.0956x over previous
#include <cuda_runtime.h>

#define T_STEPS 512
#define BATCH   4096

__device__ __align__(16) float g_h2[T_STEPS * 16];

typedef unsigned long long ull;

__device__ __forceinline__ ull ffma2(ull a, ull b, ull c) {
    ull d; asm("fma.rn.f32x2 %0, %1, %2, %3;" : "=l"(d) : "l"(a), "l"(b), "l"(c)); return d;
}
__device__ __forceinline__ ull fadd2(ull a, ull b) {
    ull d; asm("add.rn.f32x2 %0, %1, %2;" : "=l"(d) : "l"(a), "l"(b)); return d;
}
__device__ __forceinline__ float hsum2(ull a) {
    float lo, hi; asm("mov.b64 {%0, %1}, %2;" : "=f"(lo), "=f"(hi) : "l"(a)); return lo + hi;
}
__device__ __forceinline__ ull pack2(float lo, float hi) {
    ull d; asm("mov.b64 %0, {%1, %2};" : "=l"(d) : "f"(lo), "f"(hi)); return d;
}

__device__ __forceinline__ float sigf(float x) {
    return __fdividef(1.0f, 1.0f + __expf(-x));
}
__device__ __forceinline__ float tanhf_(float x) {
    return __fdividef(2.0f, 1.0f + __expf(-2.0f * x)) - 1.0f;
}

// 64 threads: warp0 = LSTM layer0 (step i), warp1 = layer1 (step i-1, pipelined).
// Within a warp: lane = u + 16*hi; hi=0 lanes own gates {i, g} and the (c,h)
// state of unit u; hi=1 lanes own gates {f, o}.
// h exchanged through double-buffered smem, ONE __syncthreads per iteration.
__global__ void __launch_bounds__(64, 1) lstm_recur_kernel(
    const float* __restrict__ x,
    const float* __restrict__ Wih0, const float* __restrict__ Whh0,
    const float* __restrict__ bih0, const float* __restrict__ bhh0,
    const float* __restrict__ Wih1, const float* __restrict__ Whh1,
    const float* __restrict__ bih1, const float* __restrict__ bhh1)
{
    __shared__ float x_sh[T_STEPS];
    __shared__ __align__(16) float hbuf[2][32];   // [parity][ h0(16) | h1(16) ]
    const int tid  = threadIdx.x;
    const int w    = tid >> 5;       // 0: layer0, 1: layer1
    const int lane = tid & 31;
    const int u    = lane & 15;
    const int hi   = lane >> 4;      // 0: gates {i,g}; 1: gates {f,o}

    // stage x[:, BATCH-1, 0]
#pragma unroll
    for (int r = 0; r < 8; r++)
        x_sh[tid + 64 * r] = x[(tid + 64 * r) * BATCH + (BATCH - 1)];
    if (tid < 32) { hbuf[0][tid] = 0.0f; hbuf[1][tid] = 0.0f; }

    const int gA = hi;        // 0 -> i, 1 -> f   (both sigmoid)
    const int gB = hi + 2;    // 0 -> g (tanh), 1 -> o (sigmoid)

    // Weight vectors over the 32-float operand [h0 | h1].
    // layer0: [Whh0 row | 0];  layer1: [Wih1 row | Whh1 row]
    ull WA[16], WB[16];
    float biasA, biasB, wxA, wxB;
    {
        const int giA = gA * 16 + u, giB = gB * 16 + u;
        if (w == 0) {
            const ull* Wp = (const ull*)Whh0;
#pragma unroll
            for (int k = 0; k < 8; k++) {
                WA[k] = Wp[giA * 8 + k];  WA[8 + k] = 0ull;
                WB[k] = Wp[giB * 8 + k];  WB[8 + k] = 0ull;
            }
            biasA = bih0[giA] + bhh0[giA];  biasB = bih0[giB] + bhh0[giB];
            wxA = Wih0[giA];                wxB = Wih0[giB];
        } else {
            const ull* Wi = (const ull*)Wih1;
            const ull* Wh = (const ull*)Whh1;
#pragma unroll
            for (int k = 0; k < 8; k++) {
                WA[k] = Wi[giA * 8 + k];  WA[8 + k] = Wh[giA * 8 + k];
                WB[k] = Wi[giB * 8 + k];  WB[8 + k] = Wh[giB * 8 + k];
            }
            biasA = bih1[giA] + bhh1[giA];  biasB = bih1[giB] + bhh1[giB];
            wxA = 0.0f;                     wxB = 0.0f;
        }
    }
    const float preB = (hi == 0) ? 2.0f : 1.0f;   // tanh vs sigmoid for gate B
    const float pm1B = preB - 1.0f;

    float h = 0.0f, c = 0.0f;
    __syncthreads();

#pragma unroll 2
    for (int i = 0; i <= T_STEPS; i++) {
        const float xv = x_sh[(i < T_STEPS) ? i : 0];

        ull op[16];
        const ulonglong2* hb = (const ulonglong2*)hbuf[i & 1];
#pragma unroll
        for (int j = 0; j < 8; j++) {
            ulonglong2 t2 = hb[j];
            op[2 * j] = t2.x;  op[2 * j + 1] = t2.y;
        }

        const float baseA = fmaf(wxA, xv, biasA);
        const float baseB = fmaf(wxB, xv, biasB);

        // 4-way split accumulator chains (depth 4) per gate
        ull aA0 = ffma2(WA[0], op[0], pack2(baseA, 0.0f));
        ull aA1 = ffma2(WA[1], op[1], 0ull);
        ull aA2 = ffma2(WA[2], op[2], 0ull);
        ull aA3 = ffma2(WA[3], op[3], 0ull);
        ull aB0 = ffma2(WB[0], op[0], pack2(baseB, 0.0f));
        ull aB1 = ffma2(WB[1], op[1], 0ull);
        ull aB2 = ffma2(WB[2], op[2], 0ull);
        ull aB3 = ffma2(WB[3], op[3], 0ull);
#pragma unroll
        for (int k = 4; k < 16; k += 4) {
            aA0 = ffma2(WA[k    ], op[k    ], aA0);
            aA1 = ffma2(WA[k + 1], op[k + 1], aA1);
            aA2 = ffma2(WA[k + 2], op[k + 2], aA2);
            aA3 = ffma2(WA[k + 3], op[k + 3], aA3);
            aB0 = ffma2(WB[k    ], op[k    ], aB0);
            aB1 = ffma2(WB[k + 1], op[k + 1], aB1);
            aB2 = ffma2(WB[k + 2], op[k + 2], aB2);
            aB3 = ffma2(WB[k + 3], op[k + 3], aB3);
        }
        const float aA = hsum2(fadd2(fadd2(aA0, aA1), fadd2(aA2, aA3)));
        const float aB = hsum2(fadd2(fadd2(aB0, aB1), fadd2(aB2, aB3)));

        const float vA = sigf(aA);                                             // i or f
        const float vB = __fdividef(preB, 1.0f + __expf(-preB * aB)) - pm1B;   // g or o

        const float fv = __shfl_sync(0xffffffffu, vA, lane | 16);   // f
        const float ov = __shfl_sync(0xffffffffu, vB, lane | 16);   // o

        const bool active = (w == 0) ? (i < T_STEPS) : (i >= 1);
        if (hi == 0 && active) {
            c = fmaf(fv, c, vA * vB);
            h = ov * tanhf_(c);
            hbuf[(i + 1) & 1][w * 16 + u] = h;
            if (w == 1) g_h2[(i - 1) * 16 + u] = h;
        }
        __syncthreads();
    }
}

// MLP 16 -> 64 (relu) -> 32 (relu) -> 1. One warp per timestep, 512 blocks,
// fully warp-synchronous (no block barriers).
__global__ void __launch_bounds__(32) mlp_kernel(
    const float* __restrict__ W1, const float* __restrict__ b1,
    const float* __restrict__ W2, const float* __restrict__ b2,
    const float* __restrict__ W3, const float* __restrict__ b3,
    float* __restrict__ out)
{
    __shared__ __align__(16) float z1sh[64];
    const int t = blockIdx.x, lane = threadIdx.x;

    const float4* hp = (const float4*)(g_h2 + t * 16);
    const float4 h4[4] = { hp[0], hp[1], hp[2], hp[3] };

    // layer1: outputs lane and lane+32
    float acc0 = b1[lane], acc1 = b1[lane + 32];
    const float4* w1a = (const float4*)(W1 + lane * 16);
    const float4* w1b = (const float4*)(W1 + (lane + 32) * 16);
#pragma unroll
    for (int q = 0; q < 4; q++) {
        const float4 wa = w1a[q], wb = w1b[q], hq = h4[q];
        acc0 = fmaf(wa.x, hq.x, acc0); acc0 = fmaf(wa.y, hq.y, acc0);
        acc0 = fmaf(wa.z, hq.z, acc0); acc0 = fmaf(wa.w, hq.w, acc0);
        acc1 = fmaf(wb.x, hq.x, acc1); acc1 = fmaf(wb.y, hq.y, acc1);
        acc1 = fmaf(wb.z, hq.z, acc1); acc1 = fmaf(wb.w, hq.w, acc1);
    }
    z1sh[lane]      = fmaxf(acc0, 0.0f);
    z1sh[lane + 32] = fmaxf(acc1, 0.0f);
    __syncwarp();

    // layer2: output `lane`; layer3 dot folded into warp reduction
    float a2 = b2[lane];
    const float4* w2p = (const float4*)(W2 + lane * 64);
    const float4* z1p = (const float4*)z1sh;
#pragma unroll
    for (int q = 0; q < 16; q++) {
        const float4 wv = w2p[q], zv = z1p[q];
        a2 = fmaf(wv.x, zv.x, a2); a2 = fmaf(wv.y, zv.y, a2);
        a2 = fmaf(wv.z, zv.z, a2); a2 = fmaf(wv.w, zv.w, a2);
    }
    float v = fmaxf(a2, 0.0f) * W3[lane];
#pragma unroll
    for (int off = 16; off; off >>= 1)
        v += __shfl_xor_sync(0xffffffffu, v, off);
    if (lane == 0) out[t] = v + b3[0];
}

extern "C" void kernel_launch(void* const* d_in, const int* in_sizes, int n_in,
                              void* d_out, int out_size)
{
    const float* x    = (const float*)d_in[0];
    const float* Wih0 = (const float*)d_in[1];
    const float* Whh0 = (const float*)d_in[2];
    const float* bih0 = (const float*)d_in[3];
    const float* bhh0 = (const float*)d_in[4];
    const float* Wih1 = (const float*)d_in[5];
    const float* Whh1 = (const float*)d_in[6];
    const float* bih1 = (const float*)d_in[7];
    const float* bhh1 = (const float*)d_in[8];
    const float* W1   = (const float*)d_in[9];
    const float* b1   = (const float*)d_in[10];
    const float* W2   = (const float*)d_in[11];
    const float* b2   = (const float*)d_in[12];
    const float* W3   = (const float*)d_in[13];
    const float* b3   = (const float*)d_in[14];
    float* out = (float*)d_out;

    lstm_recur_kernel<<<1, 64>>>(x, Wih0, Whh0, bih0, bhh0,
                                 Wih1, Whh1, bih1, bhh1);
    mlp_kernel<<<T_STEPS, 32>>>(W1, b1, W2, b2, W3, b3, out);
}